// round 2
// baseline (speedup 1.0000x reference)
#include <cuda_runtime.h>

// Problem constants (fixed for MoEDense_10411000726246)
#define TB 8192     // batch
#define DD 128      // input dim (K)
#define FF 128      // output dim (N)
#define TT 64       // num experts
#define TM 32       // rows per GEMM tile
#define NBLK 32     // preprocessing blocks (must be << 148 for resident barrier)

#define MAX_TILES (TB / TM + TT)    // 320 (worst-case padded tiles)
#define PAD_CAP   (MAX_TILES * TM)  // 10240

// Scratch (no allocations allowed)
__device__ int g_partial[NBLK * TT];
__device__ int g_arrive = 0;
__device__ int g_depart = 0;
__device__ int g_tileExpert[MAX_TILES];
__device__ int g_tileBase[MAX_TILES];
__device__ int g_tileRows[MAX_TILES];
__device__ int g_rowOrder[PAD_CAP];

// ---------------------------------------------------------------------------
// K_pre: fused histogram + scan + tile-plan + stable counting-sort scatter.
// 32 blocks x 256 threads (1 row per thread). Software grid barrier via
// atomics (all 32 blocks trivially co-resident). Barrier counters self-reset
// at the end so the kernel is replay-safe under CUDA graphs.
// ---------------------------------------------------------------------------
__global__ __launch_bounds__(256) void k_pre(const int* __restrict__ tidx) {
    __shared__ int s_bins[TT];
    __shared__ int s_total[TT];
    __shared__ int s_base[TT];
    __shared__ int s_roff[TT];
    __shared__ int s_toff[TT];
    __shared__ int s_ntiles;

    int t = threadIdx.x;
    int b = blockIdx.x;

    if (t < TT) s_bins[t] = 0;
    __syncthreads();

    // Phase 1: local histogram; each thread keeps its (expert, local rank)
    int row = b * 256 + t;
    int e = tidx[row];
    e = min(max(e, 0), TT - 1);
    int loc = atomicAdd(&s_bins[e], 1);
    __syncthreads();

    if (t < TT) g_partial[b * TT + t] = s_bins[t];
    __threadfence();
    __syncthreads();

    // Grid barrier (arrive + spin); only thread 0 spins
    if (t == 0) {
        atomicAdd(&g_arrive, 1);
        while (atomicAdd(&g_arrive, 0) < NBLK) { }
    }
    __syncthreads();
    __threadfence();

    // Phase 2: per-expert totals + this block's cross-block prefix
    if (t < TT) {
        int tot = 0, mybase = 0;
        #pragma unroll 4
        for (int i = 0; i < NBLK; i++) {
            int p = g_partial[i * TT + t];
            if (i < b) mybase += p;
            tot += p;
        }
        s_total[t] = tot;
        s_base[t] = mybase;
    }
    __syncthreads();

    // Serial scan over 64 experts (padded row offsets + tile offsets)
    if (t == 0) {
        int roff = 0, toff = 0;
        #pragma unroll
        for (int i = 0; i < TT; i++) {
            s_roff[i] = roff;
            s_toff[i] = toff;
            int nt = (s_total[i] + TM - 1) / TM;
            roff += nt * TM;
            toff += nt;
        }
        s_ntiles = toff;
    }
    __syncthreads();

    if (t < TT) s_base[t] += s_roff[t];
    __syncthreads();

    // Scatter: deterministic position, no global atomics
    g_rowOrder[s_base[e] + loc] = row;

    // Tile table (block 0 only); overwrite ALL entries every run (replay-safe)
    if (b == 0) {
        if (t < TT) {
            int tot = s_total[t];
            int nt = (tot + TM - 1) / TM;
            int tb = s_toff[t];
            int rb = s_roff[t];
            for (int j = 0; j < nt; j++) {
                g_tileExpert[tb + j] = t;
                g_tileBase[tb + j]   = rb + j * TM;
                g_tileRows[tb + j]   = min(TM, tot - j * TM);
            }
        }
        __syncthreads();
        for (int idx = s_ntiles + t; idx < MAX_TILES; idx += 256)
            g_tileExpert[idx] = -1;
    }

    // Reset barrier counters for next graph replay (last departing block)
    if (t == 0) {
        int d = atomicAdd(&g_depart, 1);
        if (d == NBLK - 1) {
            g_arrive = 0;
            g_depart = 0;
            __threadfence();
        }
    }
}

// ---------------------------------------------------------------------------
// K_gemm: grouped SGEMM. One block = one (expert, 32-row) tile, full N=128.
//   smem: As[128][32] transposed A (16KB) + Ws[128][128] weights (64KB)
//   128 threads, each computes 4 rows x 8 cols (32 fp32 accumulators).
// ---------------------------------------------------------------------------
#define SMEM_BYTES ((DD * TM + DD * FF) * 4 + TM * 4)

__global__ __launch_bounds__(128, 2)
void k_gemm(const float* __restrict__ X, const float* __restrict__ W,
            const float* __restrict__ Bias, float* __restrict__ Y) {
    extern __shared__ float smem[];
    float* As = smem;                 // [DD][TM]   transposed A
    float* Ws = smem + DD * TM;       // [DD][FF]   weights (k-major, like gmem)
    int* rows_s = (int*)(smem + DD * TM + DD * FF);

    int tile = blockIdx.x;
    int e = g_tileExpert[tile];
    if (e < 0) return;                // unused padding tile
    int base = g_tileBase[tile];
    int nrows = g_tileRows[tile];
    int tid = threadIdx.x;

    if (tid < TM) rows_s[tid] = (tid < nrows) ? g_rowOrder[base + tid] : -1;
    __syncthreads();

    // Load A (32 rows x 128 k) transposed into As[k][i]; invalid rows -> 0.
    #pragma unroll
    for (int it = 0; it < (TM * DD / 4) / 128; it++) {
        int idx = tid + it * 128;
        int i  = idx & (TM - 1);      // row in tile
        int k4 = idx >> 5;            // k/4
        int r = rows_s[i];
        float4 v = (r >= 0) ? *(const float4*)&X[r * DD + k4 * 4]
                            : make_float4(0.f, 0.f, 0.f, 0.f);
        As[(4 * k4 + 0) * TM + i] = v.x;
        As[(4 * k4 + 1) * TM + i] = v.y;
        As[(4 * k4 + 2) * TM + i] = v.z;
        As[(4 * k4 + 3) * TM + i] = v.w;
    }

    // Load W[e] (128x128 fp32 = 64KB), straight coalesced float4 copy.
    {
        const float4* Wg = (const float4*)(W + (size_t)e * DD * FF);
        float4* Wsv = (float4*)Ws;
        #pragma unroll
        for (int it = 0; it < (DD * FF / 4) / 128; it++)
            Wsv[tid + it * 128] = Wg[tid + it * 128];
    }
    __syncthreads();

    // Microkernel: thread (ri, ci) computes rows ri*4..+3, cols ci*8..+7
    int ri = tid >> 4;   // 0..7
    int ci = tid & 15;   // 0..15
    float acc[4][8];
    #pragma unroll
    for (int r = 0; r < 4; r++)
        #pragma unroll
        for (int c = 0; c < 8; c++) acc[r][c] = 0.f;

    #pragma unroll 8
    for (int k = 0; k < DD; k++) {
        float4 a  = *(const float4*)&As[k * TM + ri * 4];
        float4 b0 = *(const float4*)&Ws[k * FF + ci * 8];
        float4 b1 = *(const float4*)&Ws[k * FF + ci * 8 + 4];
        float av[4] = {a.x, a.y, a.z, a.w};
        float bv[8] = {b0.x, b0.y, b0.z, b0.w, b1.x, b1.y, b1.z, b1.w};
        #pragma unroll
        for (int r = 0; r < 4; r++)
            #pragma unroll
            for (int c = 0; c < 8; c++)
                acc[r][c] = fmaf(av[r], bv[c], acc[r][c]);
    }

    // Epilogue: add bias, store valid rows (vectorized).
    float4 bias0 = *(const float4*)&Bias[e * FF + ci * 8];
    float4 bias1 = *(const float4*)&Bias[e * FF + ci * 8 + 4];
    #pragma unroll
    for (int r = 0; r < 4; r++) {
        int row = rows_s[ri * 4 + r];
        if (row >= 0) {
            float4 o0 = make_float4(acc[r][0] + bias0.x, acc[r][1] + bias0.y,
                                    acc[r][2] + bias0.z, acc[r][3] + bias0.w);
            float4 o1 = make_float4(acc[r][4] + bias1.x, acc[r][5] + bias1.y,
                                    acc[r][6] + bias1.z, acc[r][7] + bias1.w);
            *(float4*)&Y[(size_t)row * FF + ci * 8]     = o0;
            *(float4*)&Y[(size_t)row * FF + ci * 8 + 4] = o1;
        }
    }
}

// ---------------------------------------------------------------------------
extern "C" void kernel_launch(void* const* d_in, const int* in_sizes, int n_in,
                              void* d_out, int out_size) {
    const float* X    = (const float*)d_in[0];   // [B, D] fp32
    const int*   tidx = (const int*)d_in[1];     // [B] int32
    const float* W    = (const float*)d_in[2];   // [T, D, F] fp32
    const float* Bias = (const float*)d_in[3];   // [T, F] fp32
    float* Y = (float*)d_out;                    // [B, F] fp32

    (void)in_sizes; (void)n_in; (void)out_size;

    cudaFuncSetAttribute(k_gemm, cudaFuncAttributeMaxDynamicSharedMemorySize,
                         SMEM_BYTES);

    k_pre<<<NBLK, 256>>>(tidx);
    k_gemm<<<MAX_TILES, 128, SMEM_BYTES>>>(X, W, Bias, Y);
}

// round 4
// speedup vs baseline: 1.1429x; 1.1429x over previous
#include <cuda_runtime.h>
#include <cuda_bf16.h>
#include <cstdint>

// Problem constants (fixed for MoEDense_10411000726246)
#define TB 8192     // batch
#define DD 128      // input dim (K)
#define FF 128      // output dim (N)
#define TT 64       // num experts
#define TM 128      // rows per GEMM tile
#define NBLK 32     // preprocessing blocks

#define MAX_TILES (TB / TM + TT)        // 128
#define PAD_CAP   (TB + TT * TM)        // 16384

// Scratch (no allocations allowed)
__device__ int g_partial[NBLK * TT];
__device__ int g_arrive = 0;
__device__ int g_depart = 0;
__device__ int g_tileExpert[MAX_TILES];
__device__ int g_tileBase[MAX_TILES];
__device__ int g_tileRows[MAX_TILES];
__device__ int g_rowOrder[PAD_CAP];

// ---------------------------------------------------------------------------
// K_pre: fused histogram + scan + tile-plan + stable counting-sort scatter.
// ---------------------------------------------------------------------------
__global__ __launch_bounds__(256) void k_pre(const int* __restrict__ tidx) {
    __shared__ int s_bins[TT];
    __shared__ int s_total[TT];
    __shared__ int s_base[TT];
    __shared__ int s_roff[TT];
    __shared__ int s_toff[TT];
    __shared__ int s_ntiles;

    int t = threadIdx.x;
    int b = blockIdx.x;

    if (t < TT) s_bins[t] = 0;
    __syncthreads();

    int row = b * 256 + t;
    int e = tidx[row];
    e = min(max(e, 0), TT - 1);
    int loc = atomicAdd(&s_bins[e], 1);
    __syncthreads();

    if (t < TT) g_partial[b * TT + t] = s_bins[t];
    __threadfence();
    __syncthreads();

    if (t == 0) {
        atomicAdd(&g_arrive, 1);
        while (atomicAdd(&g_arrive, 0) < NBLK) { }
    }
    __syncthreads();
    __threadfence();

    if (t < TT) {
        int tot = 0, mybase = 0;
        #pragma unroll 4
        for (int i = 0; i < NBLK; i++) {
            int p = g_partial[i * TT + t];
            if (i < b) mybase += p;
            tot += p;
        }
        s_total[t] = tot;
        s_base[t] = mybase;
    }
    __syncthreads();

    if (t == 0) {
        int roff = 0, toff = 0;
        #pragma unroll
        for (int i = 0; i < TT; i++) {
            s_roff[i] = roff;
            s_toff[i] = toff;
            int nt = (s_total[i] + TM - 1) / TM;
            roff += nt * TM;
            toff += nt;
        }
        s_ntiles = toff;
    }
    __syncthreads();

    if (t < TT) s_base[t] += s_roff[t];
    __syncthreads();

    g_rowOrder[s_base[e] + loc] = row;

    if (b == 0) {
        if (t < TT) {
            int tot = s_total[t];
            int nt = (tot + TM - 1) / TM;
            int tb = s_toff[t];
            int rb = s_roff[t];
            for (int j = 0; j < nt; j++) {
                g_tileExpert[tb + j] = t;
                g_tileBase[tb + j]   = rb + j * TM;
                g_tileRows[tb + j]   = min(TM, tot - j * TM);
            }
        }
        __syncthreads();
        for (int idx = s_ntiles + t; idx < MAX_TILES; idx += 256)
            g_tileExpert[idx] = -1;
    }

    if (t == 0) {
        int d = atomicAdd(&g_depart, 1);
        if (d == NBLK - 1) { g_arrive = 0; g_depart = 0; __threadfence(); }
    }
}

// ---------------------------------------------------------------------------
// K_gemm: mma.sync (HMMA) split-bf16 grouped GEMM.
//   One block = one (expert, 128-row) tile. 256 threads = 8 warps (4M x 2N),
//   warp tile 32x64. D = Ahi*Bhi + Alo*Bhi + Ahi*Blo, fp32 reg accumulation.
// ---------------------------------------------------------------------------
#define SPAD 136                         // padded row stride in bf16 (272 B)
#define ROWB (SPAD * 2)                  // 272 bytes
#define SM_A_HI 0
#define SM_A_LO (SM_A_HI + TM * ROWB)    // 34816
#define SM_B_HI (SM_A_LO + TM * ROWB)    // 69632
#define SM_B_LO (SM_B_HI + DD * ROWB)    // 104448
#define SM_BIAS (SM_B_LO + DD * ROWB)    // 139264
#define SM_ROWS (SM_BIAS + FF * 4)
#define SM_TOTAL (SM_ROWS + TM * 4)

__device__ __forceinline__ uint32_t smem_u32(const void* p) {
    uint32_t a;
    asm("{ .reg .u64 t; cvta.to.shared.u64 t, %1; cvt.u32.u64 %0, t; }"
        : "=r"(a) : "l"(p));
    return a;
}

#define LDSM_X4(r0, r1, r2, r3, addr)                                         \
    asm volatile("ldmatrix.sync.aligned.m8n8.x4.shared.b16 "                  \
                 "{%0,%1,%2,%3}, [%4];"                                       \
                 : "=r"(r0), "=r"(r1), "=r"(r2), "=r"(r3) : "r"(addr))

#define LDSM_X4_T(r0, r1, r2, r3, addr)                                       \
    asm volatile("ldmatrix.sync.aligned.m8n8.x4.trans.shared.b16 "            \
                 "{%0,%1,%2,%3}, [%4];"                                       \
                 : "=r"(r0), "=r"(r1), "=r"(r2), "=r"(r3) : "r"(addr))

#define MMA_16816(d, a0, a1, a2, a3, b0, b1)                                  \
    asm volatile("mma.sync.aligned.m16n8k16.row.col.f32.bf16.bf16.f32 "       \
                 "{%0,%1,%2,%3}, {%4,%5,%6,%7}, {%8,%9}, {%0,%1,%2,%3};"      \
                 : "+f"((d)[0]), "+f"((d)[1]), "+f"((d)[2]), "+f"((d)[3])     \
                 : "r"(a0), "r"(a1), "r"(a2), "r"(a3), "r"(b0), "r"(b1))

__global__ __launch_bounds__(256, 1)
void k_gemm(const float* __restrict__ X, const float* __restrict__ W,
            const float* __restrict__ Bias, float* __restrict__ Y) {
    extern __shared__ char smem[];
    const uint32_t sbase = smem_u32(smem);

    int tile = blockIdx.x;
    int e = g_tileExpert[tile];
    if (e < 0) return;
    int base  = g_tileBase[tile];
    int nrows = g_tileRows[tile];
    int tid = threadIdx.x;
    int wid = tid >> 5;
    int lid = tid & 31;

    int* rows_s   = (int*)(smem + SM_ROWS);
    float* bias_s = (float*)(smem + SM_BIAS);

    if (tid < TM) rows_s[tid] = (tid < nrows) ? g_rowOrder[base + tid] : -1;
    if (tid >= 128 && tid < 256) bias_s[tid - 128] = Bias[e * FF + (tid - 128)];
    __syncthreads();

    // --- A: gather 128 rows of X, split fp32 -> bf16 hi/lo
    #pragma unroll
    for (int it = 0; it < 16; it++) {
        int idx = tid + it * 256;             // 4096 float4s
        int m  = idx >> 5;                    // row in tile
        int c4 = idx & 31;                    // k/4
        int r = rows_s[m];
        float4 v = (r >= 0) ? *(const float4*)&X[(size_t)r * DD + c4 * 4]
                            : make_float4(0.f, 0.f, 0.f, 0.f);
        __nv_bfloat162 h01 = __float22bfloat162_rn(make_float2(v.x, v.y));
        __nv_bfloat162 h23 = __float22bfloat162_rn(make_float2(v.z, v.w));
        float2 f01 = __bfloat1622float2(h01);
        float2 f23 = __bfloat1622float2(h23);
        __nv_bfloat162 l01 = __float22bfloat162_rn(
            make_float2(v.x - f01.x, v.y - f01.y));
        __nv_bfloat162 l23 = __float22bfloat162_rn(
            make_float2(v.z - f23.x, v.w - f23.y));
        uint32_t off = (uint32_t)(m * ROWB + c4 * 8);
        uint2 hv = make_uint2(*(uint32_t*)&h01, *(uint32_t*)&h23);
        uint2 lv = make_uint2(*(uint32_t*)&l01, *(uint32_t*)&l23);
        *(uint2*)(smem + SM_A_HI + off) = hv;
        *(uint2*)(smem + SM_A_LO + off) = lv;
    }

    // --- B: W[e] is [K=128][N=128]; keep row-major (coalesced), split hi/lo
    const float* We = W + (size_t)e * DD * FF;
    #pragma unroll
    for (int it = 0; it < 16; it++) {
        int idx = tid + it * 256;             // 4096 float4s
        int k  = idx >> 5;
        int n4 = idx & 31;
        float4 v = *(const float4*)&We[(size_t)k * FF + n4 * 4];
        __nv_bfloat162 h01 = __float22bfloat162_rn(make_float2(v.x, v.y));
        __nv_bfloat162 h23 = __float22bfloat162_rn(make_float2(v.z, v.w));
        float2 f01 = __bfloat1622float2(h01);
        float2 f23 = __bfloat1622float2(h23);
        __nv_bfloat162 l01 = __float22bfloat162_rn(
            make_float2(v.x - f01.x, v.y - f01.y));
        __nv_bfloat162 l23 = __float22bfloat162_rn(
            make_float2(v.z - f23.x, v.w - f23.y));
        uint32_t off = (uint32_t)(k * ROWB + n4 * 8);
        uint2 hv = make_uint2(*(uint32_t*)&h01, *(uint32_t*)&h23);
        uint2 lv = make_uint2(*(uint32_t*)&l01, *(uint32_t*)&l23);
        *(uint2*)(smem + SM_B_HI + off) = hv;
        *(uint2*)(smem + SM_B_LO + off) = lv;
    }
    __syncthreads();

    // --- Warp tiling: wid -> (warpM 0..3, warpN 0..1); warp tile 32x64
    int warpM = wid >> 1;
    int warpN = wid & 1;

    float acc[2][8][4];
    #pragma unroll
    for (int mi = 0; mi < 2; mi++)
        #pragma unroll
        for (int nn = 0; nn < 8; nn++)
            #pragma unroll
            for (int q = 0; q < 4; q++) acc[mi][nn][q] = 0.f;

    // Per-lane ldmatrix base addresses
    // A: lane -> row (lane&15), col-block (lane>>4)*8 elements
    uint32_t aLane = (uint32_t)((warpM * 32 + (lid & 15)) * ROWB
                   + (lid >> 4) * 16);
    // B (trans): lane -> k-row (lane&15), n col n0 + (lane>>4)*8
    uint32_t bLane = (uint32_t)((lid & 15) * ROWB
                   + (warpN * 64 + (lid >> 4) * 8) * 2);

    const uint32_t aOff[3] = { SM_A_HI, SM_A_LO, SM_A_HI };
    const uint32_t bOff[3] = { SM_B_HI, SM_B_HI, SM_B_LO };

    #pragma unroll
    for (int p = 0; p < 3; p++) {
        uint32_t aBase = sbase + aOff[p] + aLane;
        uint32_t bBase = sbase + bOff[p] + bLane;
        #pragma unroll
        for (int k0 = 0; k0 < DD; k0 += 16) {
            uint32_t a[2][4];
            #pragma unroll
            for (int mi = 0; mi < 2; mi++)
                LDSM_X4(a[mi][0], a[mi][1], a[mi][2], a[mi][3],
                        aBase + mi * 16 * ROWB + k0 * 2);
            uint32_t bfr[4][4];
            #pragma unroll
            for (int jn = 0; jn < 4; jn++)
                LDSM_X4_T(bfr[jn][0], bfr[jn][1], bfr[jn][2], bfr[jn][3],
                          bBase + k0 * ROWB + jn * 32);
            #pragma unroll
            for (int mi = 0; mi < 2; mi++)
                #pragma unroll
                for (int jn = 0; jn < 4; jn++) {
                    MMA_16816(acc[mi][jn * 2],
                              a[mi][0], a[mi][1], a[mi][2], a[mi][3],
                              bfr[jn][0], bfr[jn][1]);
                    MMA_16816(acc[mi][jn * 2 + 1],
                              a[mi][0], a[mi][1], a[mi][2], a[mi][3],
                              bfr[jn][2], bfr[jn][3]);
                }
        }
    }

    // --- Epilogue: c-frag layout -> gmem with bias
    int colBase = warpN * 64 + (lid & 3) * 2;
    #pragma unroll
    for (int mi = 0; mi < 2; mi++) {
        int row0 = warpM * 32 + mi * 16 + (lid >> 2);
        int gr0 = rows_s[row0];
        int gr1 = rows_s[row0 + 8];
        #pragma unroll
        for (int nn = 0; nn < 8; nn++) {
            int col = colBase + nn * 8;
            float bx = bias_s[col], by = bias_s[col + 1];
            if (gr0 >= 0) {
                float2 o = make_float2(acc[mi][nn][0] + bx,
                                       acc[mi][nn][1] + by);
                *(float2*)&Y[(size_t)gr0 * FF + col] = o;
            }
            if (gr1 >= 0) {
                float2 o = make_float2(acc[mi][nn][2] + bx,
                                       acc[mi][nn][3] + by);
                *(float2*)&Y[(size_t)gr1 * FF + col] = o;
            }
        }
    }
}

// ---------------------------------------------------------------------------
extern "C" void kernel_launch(void* const* d_in, const int* in_sizes, int n_in,
                              void* d_out, int out_size) {
    const float* X    = (const float*)d_in[0];   // [B, D] fp32
    const int*   tidx = (const int*)d_in[1];     // [B] int32
    const float* W    = (const float*)d_in[2];   // [T, D, F] fp32
    const float* Bias = (const float*)d_in[3];   // [T, F] fp32
    float* Y = (float*)d_out;                    // [B, F] fp32

    (void)in_sizes; (void)n_in; (void)out_size;

    cudaFuncSetAttribute(k_gemm, cudaFuncAttributeMaxDynamicSharedMemorySize,
                         SM_TOTAL);

    k_pre<<<NBLK, 256>>>(tidx);
    k_gemm<<<MAX_TILES, 256, SM_TOTAL>>>(X, W, Bias, Y);
}